// round 2
// baseline (speedup 1.0000x reference)
#include <cuda_runtime.h>

// Problem constants (match reference)
#define N_ATOMS   245760
#define N_PAIRS   16777216
#define N_MOLS    4096
#define KE_CONST  138.96f

// ---------------------------------------------------------------------------
// Kernel 1: initialize output with per_system_energy * KE
// ---------------------------------------------------------------------------
__global__ void init_out_kernel(const float* __restrict__ pse,
                                float* __restrict__ out) {
    int m = blockIdx.x * blockDim.x + threadIdx.x;
    if (m < N_MOLS) out[m] = pse[m] * KE_CONST;
}

// ---------------------------------------------------------------------------
// chi(d) with the phi(2d) attenuation folded in
// ---------------------------------------------------------------------------
__device__ __forceinline__ float chi_of_d(float d) {
    // phi(u) = 1 - 6u^5 + 15u^4 - 10u^3, u = 2d, zero for u >= 1
    float u  = 2.0f * d;
    float u2 = u * u;
    float u3 = u2 * u;
    float inner = fmaf(-6.0f, u2, fmaf(15.0f, u, -10.0f));
    float phi   = fmaf(u3, inner, 1.0f);
    phi = (u < 1.0f) ? phi : 0.0f;

    float rs = rsqrtf(fmaf(d, d, 1.0f));   // 1/sqrt(d^2+1)
    float rd = __fdividef(1.0f, d);        // 1/d
    return fmaf(phi, rs - rd, rd);         // rd + phi*(rs-rd)
}

// ---------------------------------------------------------------------------
// Kernel 2: main pair loop, ILP=8, SMEM-privatized segment accumulation
// ---------------------------------------------------------------------------
__global__ __launch_bounds__(512, 2)
void coulomb_pairs_kernel(const float* __restrict__ q,
                          const int*   __restrict__ idx_i,
                          const int*   __restrict__ idx_j,
                          const float* __restrict__ d_ij,
                          const int*   __restrict__ seg,
                          float*       __restrict__ out)
{
    __shared__ float acc[N_MOLS];   // 16 KB per-block private histogram

    for (int m = threadIdx.x; m < N_MOLS; m += blockDim.x)
        acc[m] = 0.0f;
    __syncthreads();

    const int nocts  = N_PAIRS / 8;          // 8 pairs per thread-iteration
    const int stride = gridDim.x * blockDim.x;

    for (int t = blockIdx.x * blockDim.x + threadIdx.x; t < nocts; t += stride) {
        // ---- Phase 1: batch all streaming loads (evict-first) ----
        int4   vi0 = __ldcs(reinterpret_cast<const int4*>(idx_i) + 2 * t);
        int4   vi1 = __ldcs(reinterpret_cast<const int4*>(idx_i) + 2 * t + 1);
        int4   vj0 = __ldcs(reinterpret_cast<const int4*>(idx_j) + 2 * t);
        int4   vj1 = __ldcs(reinterpret_cast<const int4*>(idx_j) + 2 * t + 1);
        float4 vd0 = __ldcs(reinterpret_cast<const float4*>(d_ij) + 2 * t);
        float4 vd1 = __ldcs(reinterpret_cast<const float4*>(d_ij) + 2 * t + 1);
        int4   vs0 = __ldcs(reinterpret_cast<const int4*>(seg)   + 2 * t);
        int4   vs1 = __ldcs(reinterpret_cast<const int4*>(seg)   + 2 * t + 1);

        // ---- Phase 2: batch all 16 gathers (default caching: keep L1) ----
        float qi0 = __ldg(q + vi0.x), qj0 = __ldg(q + vj0.x);
        float qi1 = __ldg(q + vi0.y), qj1 = __ldg(q + vj0.y);
        float qi2 = __ldg(q + vi0.z), qj2 = __ldg(q + vj0.z);
        float qi3 = __ldg(q + vi0.w), qj3 = __ldg(q + vj0.w);
        float qi4 = __ldg(q + vi1.x), qj4 = __ldg(q + vj1.x);
        float qi5 = __ldg(q + vi1.y), qj5 = __ldg(q + vj1.y);
        float qi6 = __ldg(q + vi1.z), qj6 = __ldg(q + vj1.z);
        float qi7 = __ldg(q + vi1.w), qj7 = __ldg(q + vj1.w);

        // ---- Phase 3: compute + scatter ----
        float c0 = qi0 * qj0 * chi_of_d(vd0.x);
        float c1 = qi1 * qj1 * chi_of_d(vd0.y);
        float c2 = qi2 * qj2 * chi_of_d(vd0.z);
        float c3 = qi3 * qj3 * chi_of_d(vd0.w);
        float c4 = qi4 * qj4 * chi_of_d(vd1.x);
        float c5 = qi5 * qj5 * chi_of_d(vd1.y);
        float c6 = qi6 * qj6 * chi_of_d(vd1.z);
        float c7 = qi7 * qj7 * chi_of_d(vd1.w);

        if (vi0.x < vj0.x) atomicAdd(&acc[vs0.x], c0);
        if (vi0.y < vj0.y) atomicAdd(&acc[vs0.y], c1);
        if (vi0.z < vj0.z) atomicAdd(&acc[vs0.z], c2);
        if (vi0.w < vj0.w) atomicAdd(&acc[vs0.w], c3);
        if (vi1.x < vj1.x) atomicAdd(&acc[vs1.x], c4);
        if (vi1.y < vj1.y) atomicAdd(&acc[vs1.y], c5);
        if (vi1.z < vj1.z) atomicAdd(&acc[vs1.z], c6);
        if (vi1.w < vj1.w) atomicAdd(&acc[vs1.w], c7);
    }

    __syncthreads();

    // Flush block-private histogram to global (out already holds pse*KE)
    for (int m = threadIdx.x; m < N_MOLS; m += blockDim.x) {
        float v = acc[m];
        if (v != 0.0f)
            atomicAdd(&out[m], v * KE_CONST);
    }
}

// ---------------------------------------------------------------------------
// Launch
// ---------------------------------------------------------------------------
extern "C" void kernel_launch(void* const* d_in, const int* in_sizes, int n_in,
                              void* d_out, int out_size) {
    const float* q    = (const float*)d_in[0];           // per_atom_charge [N_ATOMS]
    const int*   pidx = (const int*)  d_in[1];           // pair_indices [2, N_PAIRS]
    const float* dij  = (const float*)d_in[2];           // d_ij [N_PAIRS]
    const int*   seg  = (const int*)  d_in[3];           // atomic_subsystem_indices [N_PAIRS]
    const float* pse  = (const float*)d_in[4];           // per_system_energy [N_MOLS]
    float* out = (float*)d_out;

    const int* idx_i = pidx;
    const int* idx_j = pidx + N_PAIRS;

    init_out_kernel<<<(N_MOLS + 255) / 256, 256>>>(pse, out);

    // 2 blocks/SM x 148 SMs, 512 threads — 16 KB SMEM/block histogram,
    // leaves ~196 KB L1D carveout for the 960 KB charge-table gathers.
    const int blocks  = 296;
    const int threads = 512;
    coulomb_pairs_kernel<<<blocks, threads>>>(q, idx_i, idx_j, dij, seg, out);
}